// round 4
// baseline (speedup 1.0000x reference)
#include <cuda_runtime.h>
#include <cuda_bf16.h>
#include <math_constants.h>

#define B_  256
#define S_  128
#define D_  768
#define MASK_ID_ 103

// Scratch (no allocation allowed -> device globals)
__device__ float g_feats[B_ * 2 * D_];   // [att | mask_logits], 256 x 1536
__device__ float g_h[B_ * D_];           // tanh(dense) output, 256 x 768
__device__ float g_sraw[B_ * S_];        // raw scores, 256 x 128

__constant__ int c_label_ids[21] = {
    2307, 2204, 3835, 2157, 6581, 2986, 5151, 3893,
    7929, 24791, 8699, 4257, 16021, 6623,
    6659, 2919, 11771, 3532, 11325, 4997, 13135
};

__device__ __forceinline__ float warp_sum(float v) {
    #pragma unroll
    for (int o = 16; o; o >>= 1) v += __shfl_xor_sync(0xffffffffu, v, o);
    return v;
}
__device__ __forceinline__ float warp_max(float v) {
    #pragma unroll
    for (int o = 16; o; o >>= 1) v = fmaxf(v, __shfl_xor_sync(0xffffffffu, v, o));
    return v;
}

// ---------------------------------------------------------------------------
// Kernel 1a: scores_raw[b,s] = dot(bert[b,s,:], bert[b,mpos,:])
// grid = (4 s-chunks, 256 batches), block = 256 (8 warps, 4 rows each)
// Chunk 0 also: category_out and feats[b][D:2D] = mask_logits.
// ---------------------------------------------------------------------------
__global__ __launch_bounds__(256) void k1a_scores(
    const float* __restrict__ bert,
    const int*   __restrict__ input_ids,
    const float* __restrict__ senti_w,
    const float* __restrict__ senti_b,
    float*       __restrict__ d_out,
    float*       __restrict__ feats,
    float*       __restrict__ sraw_g)
{
    const int b     = blockIdx.y;
    const int chunk = blockIdx.x;
    const int tid   = threadIdx.x;
    const int warp  = tid >> 5;
    const int lane  = tid & 31;

    __shared__ float ml[D_];
    __shared__ int   mpos;

    if (tid == 0) mpos = 0x7fffffff;
    __syncthreads();
    if (tid < S_ && input_ids[b * S_ + tid] == MASK_ID_) atomicMin(&mpos, tid);
    __syncthreads();
    const int mp = mpos;

    const float* base = bert + (size_t)b * (S_ * D_);

    // mask_logits -> smem (192 float4)
    if (tid < 192)
        ((float4*)ml)[tid] = ((const float4*)(base + (size_t)mp * D_))[tid];
    __syncthreads();

    // 4 rows per warp, float4 loads, independent accumulators
    const int s0 = chunk * 32 + warp * 4;
    const float4* r0 = (const float4*)(base + (size_t)(s0 + 0) * D_);
    const float4* r1 = (const float4*)(base + (size_t)(s0 + 1) * D_);
    const float4* r2 = (const float4*)(base + (size_t)(s0 + 2) * D_);
    const float4* r3 = (const float4*)(base + (size_t)(s0 + 3) * D_);
    const float4* m4 = (const float4*)ml;

    float a0 = 0.f, a1 = 0.f, a2 = 0.f, a3 = 0.f;
    #pragma unroll
    for (int i = 0; i < 6; i++) {
        const int q = lane + i * 32;
        const float4 m = m4[q];
        float4 v;
        v = r0[q]; a0 = fmaf(v.x, m.x, fmaf(v.y, m.y, fmaf(v.z, m.z, fmaf(v.w, m.w, a0))));
        v = r1[q]; a1 = fmaf(v.x, m.x, fmaf(v.y, m.y, fmaf(v.z, m.z, fmaf(v.w, m.w, a1))));
        v = r2[q]; a2 = fmaf(v.x, m.x, fmaf(v.y, m.y, fmaf(v.z, m.z, fmaf(v.w, m.w, a2))));
        v = r3[q]; a3 = fmaf(v.x, m.x, fmaf(v.y, m.y, fmaf(v.z, m.z, fmaf(v.w, m.w, a3))));
    }
    a0 = warp_sum(a0); a1 = warp_sum(a1); a2 = warp_sum(a2); a3 = warp_sum(a3);
    if (lane == 0) {
        float* o = sraw_g + b * S_ + s0;
        o[0] = a0; o[1] = a1; o[2] = a2; o[3] = a3;
    }

    if (chunk == 0) {
        // feats upper half = mask_logits
        float* fb = feats + (size_t)b * (2 * D_);
        if (tid < 192) ((float4*)(fb + D_))[tid] = m4[tid];

        // category_out: pooler = bert[b,0,:]
        if (warp < 2) {
            const float4* p4 = (const float4*)base;
            const float4* w4 = (const float4*)(senti_w + warp * D_);
            float acc = 0.f;
            #pragma unroll
            for (int i = 0; i < 6; i++) {
                const int q = lane + i * 32;
                float4 p = p4[q], w = w4[q];
                acc = fmaf(p.x, w.x, fmaf(p.y, w.y, fmaf(p.z, w.z, fmaf(p.w, w.w, acc))));
            }
            acc = warp_sum(acc);
            if (lane == 0) d_out[b * 2 + warp] = acc + senti_b[warp];
        }
    }
}

// ---------------------------------------------------------------------------
// Kernel 1b: softmax (recomputed per chunk) + att; feats[b][0:D] = att.
// grid = (3 d-chunks of 256, 256 batches), block = 256
// ---------------------------------------------------------------------------
__global__ __launch_bounds__(256) void k1b_att(
    const float* __restrict__ bert,
    const int*   __restrict__ length,
    const float* __restrict__ sraw_g,
    float*       __restrict__ feats)
{
    const int b    = blockIdx.y;
    const int d0   = blockIdx.x * 256;
    const int tid  = threadIdx.x;
    const int warp = tid >> 5;
    const int lane = tid & 31;

    __shared__ float sc[S_];
    __shared__ float red[2];

    if (tid < S_) sc[tid] = sraw_g[b * S_ + tid];
    __syncthreads();

    const int L = length[b];

    if (warp == 0) {
        float m = -CUDART_INF_F;
        #pragma unroll
        for (int i = 0; i < 4; i++) {
            int s = lane + 32 * i;
            if (s >= 3 && s < 3 + L) m = fmaxf(m, sc[s]);
        }
        m = warp_max(m);
        float sum = 0.f;
        #pragma unroll
        for (int i = 0; i < 4; i++) {
            int s = lane + 32 * i;
            if (s >= 3 && s < 3 + L) sum += __expf(sc[s] - m);
        }
        sum = warp_sum(sum);
        if (lane == 0) { red[0] = m; red[1] = sum; }
    }
    __syncthreads();
    {
        const float m   = red[0];
        const float inv = 1.0f / red[1];
        if (tid < S_) {
            int s = tid;
            bool v = (s >= 3) && (s < 3 + L);
            sc[s] = v ? __expf(sc[s] - m) * inv : 0.f;
        }
    }
    __syncthreads();

    const float* col = bert + (size_t)b * (S_ * D_) + d0 + tid;
    float acc = 0.f;
    #pragma unroll 8
    for (int s = 0; s < S_; s++) {
        acc = fmaf(sc[s], col[(size_t)s * D_], acc);
    }
    feats[(size_t)b * (2 * D_) + d0 + tid] = acc;
}

// ---------------------------------------------------------------------------
// Kernel 2: h = tanh(feats @ dense_w^T + dense_b)
// M=256, N=768, K=1536. BM=32, BN=48, BK=32; 2x3 micro; grid 8x16 = 128 CTAs
// ---------------------------------------------------------------------------
#define BM 32
#define BN 48
#define BK 32
#define KDIM 1536
#define NDIM 768

__global__ __launch_bounds__(256) void k2_dense(
    const float* __restrict__ A,
    const float* __restrict__ Bw,
    const float* __restrict__ bias,
    float*       __restrict__ H)
{
    __shared__ float As[BM][BK];
    __shared__ float Bs[BK][BN + 1];

    const int m0  = blockIdx.x * BM;
    const int n0  = blockIdx.y * BN;
    const int tid = threadIdx.x;
    const int tx  = tid & 15;
    const int ty  = tid >> 4;

    float acc[2][3] = {{0.f,0.f,0.f},{0.f,0.f,0.f}};

    for (int k0 = 0; k0 < KDIM; k0 += BK) {
        {
            int r = tid >> 3, c = tid & 7;
            float4 v = *(const float4*)(A + (size_t)(m0 + r) * KDIM + k0 + c * 4);
            *(float4*)&As[r][c * 4] = v;
        }
        {
            int idx = tid;
            int n = idx >> 3, c = idx & 7;
            float4 v = *(const float4*)(Bw + (size_t)(n0 + n) * KDIM + k0 + c * 4);
            Bs[c * 4 + 0][n] = v.x; Bs[c * 4 + 1][n] = v.y;
            Bs[c * 4 + 2][n] = v.z; Bs[c * 4 + 3][n] = v.w;
            if (tid < 128) {
                idx = tid + 256;
                n = idx >> 3; c = idx & 7;
                float4 v2 = *(const float4*)(Bw + (size_t)(n0 + n) * KDIM + k0 + c * 4);
                Bs[c * 4 + 0][n] = v2.x; Bs[c * 4 + 1][n] = v2.y;
                Bs[c * 4 + 2][n] = v2.z; Bs[c * 4 + 3][n] = v2.w;
            }
        }
        __syncthreads();

        #pragma unroll
        for (int k = 0; k < BK; k++) {
            float a0 = As[ty * 2 + 0][k];
            float a1 = As[ty * 2 + 1][k];
            float b0 = Bs[k][tx * 3 + 0];
            float b1 = Bs[k][tx * 3 + 1];
            float b2 = Bs[k][tx * 3 + 2];
            acc[0][0] = fmaf(a0, b0, acc[0][0]);
            acc[0][1] = fmaf(a0, b1, acc[0][1]);
            acc[0][2] = fmaf(a0, b2, acc[0][2]);
            acc[1][0] = fmaf(a1, b0, acc[1][0]);
            acc[1][1] = fmaf(a1, b1, acc[1][1]);
            acc[1][2] = fmaf(a1, b2, acc[1][2]);
        }
        __syncthreads();
    }

    #pragma unroll
    for (int i = 0; i < 2; i++) {
        int m = m0 + ty * 2 + i;
        #pragma unroll
        for (int j = 0; j < 3; j++) {
            int n = n0 + tx * 3 + j;
            H[(size_t)m * NDIM + n] = tanhf(acc[i][j] + bias[n]);
        }
    }
}

// ---------------------------------------------------------------------------
// Kernel 3: probs at the 21 label ids + tiny head GEMMs.
// ---------------------------------------------------------------------------
__global__ __launch_bounds__(256) void k3_decoder(
    const float* __restrict__ h,
    const float* __restrict__ dec_w,
    const float* __restrict__ dec_b,
    const float* __restrict__ w0,
    const float* __restrict__ w1,
    const float* __restrict__ w2,
    float*       __restrict__ d_out)
{
    const int b    = blockIdx.x;
    const int tid  = threadIdx.x;
    const int warp = tid >> 5;
    const int lane = tid & 31;

    __shared__ float probs[21];
    const float* hb = h + (size_t)b * D_;

    for (int i = warp; i < 21; i += 8) {
        const int id = c_label_ids[i];
        const float4* r4 = (const float4*)(dec_w + (size_t)id * D_);
        const float4* h4 = (const float4*)hb;
        float acc = 0.f;
        #pragma unroll
        for (int t = 0; t < 6; t++) {
            int q = lane + 32 * t;
            float4 r = r4[q], hh = h4[q];
            acc = fmaf(r.x, hh.x, fmaf(r.y, hh.y, fmaf(r.z, hh.z, fmaf(r.w, hh.w, acc))));
        }
        acc = warp_sum(acc);
        if (lane == 0) probs[i] = tanhf(acc + dec_b[id]);
    }
    __syncthreads();

    if (tid < 6) {
        const int j = tid >> 1;
        const int i = tid & 1;
        const float* w   = (j == 0) ? w0 : (j == 1) ? w1 : w2;
        const int    off = (j == 0) ? 0  : (j == 1) ? 8  : 14;
        const int    n   = (j == 0) ? 8  : (j == 1) ? 6  : 7;
        float acc = 0.f;
        for (int l = 0; l < n; l++) acc += w[i * n + l] * probs[off + l];
        d_out[512 + b * 6 + i * 3 + j] = acc;
    }
}

// ---------------------------------------------------------------------------
extern "C" void kernel_launch(void* const* d_in, const int* in_sizes, int n_in,
                              void* d_out, int out_size)
{
    const float* bert      = (const float*)d_in[0];
    const int*   input_ids = (const int*)  d_in[1];
    const int*   length    = (const int*)  d_in[2];
    const float* senti_w   = (const float*)d_in[3];
    const float* senti_b   = (const float*)d_in[4];
    const float* dense_w   = (const float*)d_in[5];
    const float* dense_b   = (const float*)d_in[6];
    const float* dec_w     = (const float*)d_in[7];
    const float* dec_b     = (const float*)d_in[8];
    const float* w0        = (const float*)d_in[9];
    const float* w1        = (const float*)d_in[10];
    const float* w2        = (const float*)d_in[11];
    float* out = (float*)d_out;

    float* feats; cudaGetSymbolAddress((void**)&feats, g_feats);
    float* hbuf;  cudaGetSymbolAddress((void**)&hbuf,  g_h);
    float* sraw;  cudaGetSymbolAddress((void**)&sraw,  g_sraw);

    k1a_scores<<<dim3(4, B_), 256>>>(bert, input_ids, senti_w, senti_b, out, feats, sraw);
    k1b_att   <<<dim3(3, B_), 256>>>(bert, length, sraw, feats);
    k2_dense  <<<dim3(B_ / BM, NDIM / BN), 256>>>(feats, dense_w, dense_b, hbuf);
    k3_decoder<<<B_, 256>>>(hbuf, dec_w, dec_b, w0, w1, w2, out);
}

// round 5
// speedup vs baseline: 1.0314x; 1.0314x over previous
#include <cuda_runtime.h>
#include <cuda_bf16.h>
#include <math_constants.h>

#define B_  256
#define S_  128
#define D_  768
#define MASK_ID_ 103

// Scratch (no allocation allowed -> device globals)
__device__ float g_feats[B_ * 2 * D_];   // [att | mask_logits], 256 x 1536
__device__ float g_h[B_ * D_];           // tanh(dense) output, 256 x 768
__device__ float g_sraw[B_ * S_];        // raw scores, 256 x 128

__constant__ int c_label_ids[21] = {
    2307, 2204, 3835, 2157, 6581, 2986, 5151, 3893,
    7929, 24791, 8699, 4257, 16021, 6623,
    6659, 2919, 11771, 3532, 11325, 4997, 13135
};

__device__ __forceinline__ float warp_sum(float v) {
    #pragma unroll
    for (int o = 16; o; o >>= 1) v += __shfl_xor_sync(0xffffffffu, v, o);
    return v;
}
__device__ __forceinline__ float warp_max(float v) {
    #pragma unroll
    for (int o = 16; o; o >>= 1) v = fmaxf(v, __shfl_xor_sync(0xffffffffu, v, o));
    return v;
}

#define FMA_F32X2(acc, a, b) \
    asm("fma.rn.f32x2 %0, %1, %2, %0;" : "+l"(acc) : "l"(a), "l"(b))

__device__ __forceinline__ float dot4(float4 a, float4 b, float acc) {
    return fmaf(a.x, b.x, fmaf(a.y, b.y, fmaf(a.z, b.z, fmaf(a.w, b.w, acc))));
}

// ---------------------------------------------------------------------------
// Kernel 1a: scores_raw[b,s] = dot(bert[b,s,:], bert[b,mpos,:])
// grid = (16 s-chunks, 256 batches), block = 256: ONE WARP PER ROW.
// Each warp issues 6 independent LDG.128 (guaranteed MLP=6) then reduces.
// Chunk 0 additionally writes feats[b][D:2D] = mask_logits and category_out.
// ---------------------------------------------------------------------------
__global__ __launch_bounds__(256) void k1a_scores(
    const float* __restrict__ bert,
    const int*   __restrict__ input_ids,
    const float* __restrict__ senti_w,
    const float* __restrict__ senti_b,
    float*       __restrict__ d_out,
    float*       __restrict__ feats,
    float*       __restrict__ sraw_g)
{
    const int b    = blockIdx.y;
    const int tid  = threadIdx.x;
    const int warp = tid >> 5;
    const int lane = tid & 31;

    __shared__ float ml[D_];
    __shared__ int   mpos;

    if (tid == 0) mpos = 0x7fffffff;
    __syncthreads();
    if (tid < S_ && input_ids[b * S_ + tid] == MASK_ID_) atomicMin(&mpos, tid);
    __syncthreads();
    const int mp = mpos;

    const float* base = bert + (size_t)b * (S_ * D_);

    if (tid < 192)
        ((float4*)ml)[tid] = ((const float4*)(base + (size_t)mp * D_))[tid];
    __syncthreads();

    // one row per warp: 6 independent float4 loads, all issued before use
    const int s = blockIdx.x * 8 + warp;
    const float4* r4 = (const float4*)(base + (size_t)s * D_);
    const float4* m4 = (const float4*)ml;

    float4 v0 = r4[lane];
    float4 v1 = r4[lane + 32];
    float4 v2 = r4[lane + 64];
    float4 v3 = r4[lane + 96];
    float4 v4 = r4[lane + 128];
    float4 v5 = r4[lane + 160];

    float acc = 0.f;
    acc = dot4(v0, m4[lane],       acc);
    acc = dot4(v1, m4[lane + 32],  acc);
    acc = dot4(v2, m4[lane + 64],  acc);
    acc = dot4(v3, m4[lane + 96],  acc);
    acc = dot4(v4, m4[lane + 128], acc);
    acc = dot4(v5, m4[lane + 160], acc);
    acc = warp_sum(acc);
    if (lane == 0) sraw_g[b * S_ + s] = acc;

    if (blockIdx.x == 0) {
        // feats upper half = mask_logits
        float* fb = feats + (size_t)b * (2 * D_);
        if (tid < 192) ((float4*)(fb + D_))[tid] = m4[tid];

        // category_out: pooler = bert[b,0,:] (row 0 is hot in L1 from warp 0)
        if (warp < 2) {
            const float4* p4 = (const float4*)base;
            const float4* w4 = (const float4*)(senti_w + warp * D_);
            float4 p0 = p4[lane],       p1 = p4[lane + 32],  p2 = p4[lane + 64];
            float4 p3 = p4[lane + 96],  p4v = p4[lane + 128], p5 = p4[lane + 160];
            float4 w0 = w4[lane],       w1 = w4[lane + 32],  w2 = w4[lane + 64];
            float4 w3 = w4[lane + 96],  w4v = w4[lane + 128], w5 = w4[lane + 160];
            float c = 0.f;
            c = dot4(p0, w0, c); c = dot4(p1, w1, c); c = dot4(p2, w2, c);
            c = dot4(p3, w3, c); c = dot4(p4v, w4v, c); c = dot4(p5, w5, c);
            c = warp_sum(c);
            if (lane == 0) d_out[b * 2 + warp] = c + senti_b[warp];
        }
    }
}

// ---------------------------------------------------------------------------
// Kernel 1b: softmax (recomputed per chunk) + att; feats[b][0:D] = att.
// grid = (3 d-chunks of 256, 256 batches), block = 256.
// att loop: explicit 16-load batches (guaranteed MLP=16), 4 accumulators.
// ---------------------------------------------------------------------------
__global__ __launch_bounds__(256) void k1b_att(
    const float* __restrict__ bert,
    const int*   __restrict__ length,
    const float* __restrict__ sraw_g,
    float*       __restrict__ feats)
{
    const int b    = blockIdx.y;
    const int d0   = blockIdx.x * 256;
    const int tid  = threadIdx.x;
    const int warp = tid >> 5;
    const int lane = tid & 31;

    __shared__ float sc[S_];
    __shared__ float red[2];

    if (tid < S_) sc[tid] = sraw_g[b * S_ + tid];
    __syncthreads();

    const int L = length[b];

    if (warp == 0) {
        float m = -CUDART_INF_F;
        #pragma unroll
        for (int i = 0; i < 4; i++) {
            int s = lane + 32 * i;
            if (s >= 3 && s < 3 + L) m = fmaxf(m, sc[s]);
        }
        m = warp_max(m);
        float sum = 0.f;
        #pragma unroll
        for (int i = 0; i < 4; i++) {
            int s = lane + 32 * i;
            if (s >= 3 && s < 3 + L) sum += __expf(sc[s] - m);
        }
        sum = warp_sum(sum);
        if (lane == 0) { red[0] = m; red[1] = sum; }
    }
    __syncthreads();
    {
        const float m   = red[0];
        const float inv = 1.0f / red[1];
        if (tid < S_) {
            int s = tid;
            bool v = (s >= 3) && (s < 3 + L);
            sc[s] = v ? __expf(sc[s] - m) * inv : 0.f;
        }
    }
    __syncthreads();

    const float* col = bert + (size_t)b * (S_ * D_) + d0 + tid;
    float a0 = 0.f, a1 = 0.f, a2 = 0.f, a3 = 0.f;
    #pragma unroll 1
    for (int s0 = 0; s0 < S_; s0 += 16) {
        float x0  = col[(size_t)(s0 +  0) * D_];
        float x1  = col[(size_t)(s0 +  1) * D_];
        float x2  = col[(size_t)(s0 +  2) * D_];
        float x3  = col[(size_t)(s0 +  3) * D_];
        float x4  = col[(size_t)(s0 +  4) * D_];
        float x5  = col[(size_t)(s0 +  5) * D_];
        float x6  = col[(size_t)(s0 +  6) * D_];
        float x7  = col[(size_t)(s0 +  7) * D_];
        float x8  = col[(size_t)(s0 +  8) * D_];
        float x9  = col[(size_t)(s0 +  9) * D_];
        float x10 = col[(size_t)(s0 + 10) * D_];
        float x11 = col[(size_t)(s0 + 11) * D_];
        float x12 = col[(size_t)(s0 + 12) * D_];
        float x13 = col[(size_t)(s0 + 13) * D_];
        float x14 = col[(size_t)(s0 + 14) * D_];
        float x15 = col[(size_t)(s0 + 15) * D_];
        a0 = fmaf(sc[s0 +  0], x0,  a0);  a1 = fmaf(sc[s0 +  1], x1,  a1);
        a2 = fmaf(sc[s0 +  2], x2,  a2);  a3 = fmaf(sc[s0 +  3], x3,  a3);
        a0 = fmaf(sc[s0 +  4], x4,  a0);  a1 = fmaf(sc[s0 +  5], x5,  a1);
        a2 = fmaf(sc[s0 +  6], x6,  a2);  a3 = fmaf(sc[s0 +  7], x7,  a3);
        a0 = fmaf(sc[s0 +  8], x8,  a0);  a1 = fmaf(sc[s0 +  9], x9,  a1);
        a2 = fmaf(sc[s0 + 10], x10, a2);  a3 = fmaf(sc[s0 + 11], x11, a3);
        a0 = fmaf(sc[s0 + 12], x12, a0);  a1 = fmaf(sc[s0 + 13], x13, a1);
        a2 = fmaf(sc[s0 + 14], x14, a2);  a3 = fmaf(sc[s0 + 15], x15, a3);
    }
    feats[(size_t)b * (2 * D_) + d0 + tid] = (a0 + a1) + (a2 + a3);
}

// ---------------------------------------------------------------------------
// Kernel 2: h = tanh(feats @ dense_w^T + dense_b) via packed fma.rn.f32x2.
// M=256, N=768, K=1536. BM=32, BN=48, BK=32; grid 8x16 = 128 CTAs.
// Micro-tile per thread: one m-pair (2 rows) x 3 n. Accumulators are f32x2.
// As stored k-major as m-pairs; Bs stored as duplicated {b,b} pairs.
// ---------------------------------------------------------------------------
#define BM 32
#define BN 48
#define BK 32
#define KDIM 1536
#define NDIM 768

__global__ __launch_bounds__(256) void k2_dense(
    const float* __restrict__ A,
    const float* __restrict__ Bw,
    const float* __restrict__ bias,
    float*       __restrict__ H)
{
    // As2u[k][m2]: ull = {A[m0+2*m2][k], A[m0+2*m2+1][k]}, row padded 16->17
    // Bsdu[k][n]:  ull = {Bw[n0+n][k], Bw[n0+n][k]} duplicated, row padded 48->49
    __shared__ unsigned long long As2u[BK * 17];
    __shared__ unsigned long long Bsdu[BK * 49];

    const int m0  = blockIdx.x * BM;
    const int n0  = blockIdx.y * BN;
    const int tid = threadIdx.x;
    const int tx  = tid & 15;
    const int ty  = tid >> 4;

    float* Asf = (float*)As2u;   // layout: [k][m] with 34-float row stride

    unsigned long long acc0 = 0ull, acc1 = 0ull, acc2 = 0ull;

    for (int k0 = 0; k0 < KDIM; k0 += BK) {
        // A tile: 32 rows x 32 k (256 float4), store transposed k-major
        {
            int r = tid >> 3, c = tid & 7;
            float4 v = *(const float4*)(A + (size_t)(m0 + r) * KDIM + k0 + c * 4);
            Asf[(c * 4 + 0) * 34 + r] = v.x;
            Asf[(c * 4 + 1) * 34 + r] = v.y;
            Asf[(c * 4 + 2) * 34 + r] = v.z;
            Asf[(c * 4 + 3) * 34 + r] = v.w;
        }
        // B tile: 48 rows x 32 k (384 float4), store duplicated pairs
        {
            int n = tid >> 3, c = tid & 7;
            float4 v = *(const float4*)(Bw + (size_t)(n0 + n) * KDIM + k0 + c * 4);
            ((float2*)Bsdu)[(c * 4 + 0) * 49 + n] = make_float2(v.x, v.x);
            ((float2*)Bsdu)[(c * 4 + 1) * 49 + n] = make_float2(v.y, v.y);
            ((float2*)Bsdu)[(c * 4 + 2) * 49 + n] = make_float2(v.z, v.z);
            ((float2*)Bsdu)[(c * 4 + 3) * 49 + n] = make_float2(v.w, v.w);
            if (tid < 128) {
                int idx = tid + 256;
                n = idx >> 3; c = idx & 7;
                float4 w = *(const float4*)(Bw + (size_t)(n0 + n) * KDIM + k0 + c * 4);
                ((float2*)Bsdu)[(c * 4 + 0) * 49 + n] = make_float2(w.x, w.x);
                ((float2*)Bsdu)[(c * 4 + 1) * 49 + n] = make_float2(w.y, w.y);
                ((float2*)Bsdu)[(c * 4 + 2) * 49 + n] = make_float2(w.z, w.z);
                ((float2*)Bsdu)[(c * 4 + 3) * 49 + n] = make_float2(w.w, w.w);
            }
        }
        __syncthreads();

        #pragma unroll
        for (int k = 0; k < BK; k++) {
            unsigned long long a2 = As2u[k * 17 + ty];
            unsigned long long b0 = Bsdu[k * 49 + tx * 3 + 0];
            unsigned long long b1 = Bsdu[k * 49 + tx * 3 + 1];
            unsigned long long b2 = Bsdu[k * 49 + tx * 3 + 2];
            FMA_F32X2(acc0, a2, b0);
            FMA_F32X2(acc1, a2, b1);
            FMA_F32X2(acc2, a2, b2);
        }
        __syncthreads();
    }

    // epilogue: unpack pairs {row 2ty, row 2ty+1}
    unsigned long long accs[3] = {acc0, acc1, acc2};
    #pragma unroll
    for (int j = 0; j < 3; j++) {
        unsigned int lo, hi;
        asm("mov.b64 {%0, %1}, %2;" : "=r"(lo), "=r"(hi) : "l"(accs[j]));
        int n = n0 + tx * 3 + j;
        float bv = bias[n];
        H[(size_t)(m0 + ty * 2 + 0) * NDIM + n] = tanhf(__uint_as_float(lo) + bv);
        H[(size_t)(m0 + ty * 2 + 1) * NDIM + n] = tanhf(__uint_as_float(hi) + bv);
    }
}

// ---------------------------------------------------------------------------
// Kernel 3: probs at the 21 label ids + tiny head GEMMs.
// block = 672 (21 warps, one per label) -> single round, batched loads.
// ---------------------------------------------------------------------------
__global__ __launch_bounds__(672) void k3_decoder(
    const float* __restrict__ h,
    const float* __restrict__ dec_w,
    const float* __restrict__ dec_b,
    const float* __restrict__ w0,
    const float* __restrict__ w1,
    const float* __restrict__ w2,
    float*       __restrict__ d_out)
{
    const int b    = blockIdx.x;
    const int tid  = threadIdx.x;
    const int warp = tid >> 5;
    const int lane = tid & 31;

    __shared__ float hs[D_];
    __shared__ float probs[21];

    if (tid < 192)
        ((float4*)hs)[tid] = ((const float4*)(h + (size_t)b * D_))[tid];
    __syncthreads();

    {
        const int id = c_label_ids[warp];
        const float4* r4 = (const float4*)(dec_w + (size_t)id * D_);
        const float4* h4 = (const float4*)hs;
        float4 v0 = r4[lane];
        float4 v1 = r4[lane + 32];
        float4 v2 = r4[lane + 64];
        float4 v3 = r4[lane + 96];
        float4 v4 = r4[lane + 128];
        float4 v5 = r4[lane + 160];
        float acc = 0.f;
        acc = dot4(v0, h4[lane],       acc);
        acc = dot4(v1, h4[lane + 32],  acc);
        acc = dot4(v2, h4[lane + 64],  acc);
        acc = dot4(v3, h4[lane + 96],  acc);
        acc = dot4(v4, h4[lane + 128], acc);
        acc = dot4(v5, h4[lane + 160], acc);
        acc = warp_sum(acc);
        if (lane == 0) probs[warp] = tanhf(acc + dec_b[id]);
    }
    __syncthreads();

    if (tid < 6) {
        const int j = tid >> 1;
        const int i = tid & 1;
        const float* w   = (j == 0) ? w0 : (j == 1) ? w1 : w2;
        const int    off = (j == 0) ? 0  : (j == 1) ? 8  : 14;
        const int    n   = (j == 0) ? 8  : (j == 1) ? 6  : 7;
        float acc = 0.f;
        for (int l = 0; l < n; l++) acc += w[i * n + l] * probs[off + l];
        d_out[512 + b * 6 + i * 3 + j] = acc;
    }
}

// ---------------------------------------------------------------------------
extern "C" void kernel_launch(void* const* d_in, const int* in_sizes, int n_in,
                              void* d_out, int out_size)
{
    const float* bert      = (const float*)d_in[0];
    const int*   input_ids = (const int*)  d_in[1];
    const int*   length    = (const int*)  d_in[2];
    const float* senti_w   = (const float*)d_in[3];
    const float* senti_b   = (const float*)d_in[4];
    const float* dense_w   = (const float*)d_in[5];
    const float* dense_b   = (const float*)d_in[6];
    const float* dec_w     = (const float*)d_in[7];
    const float* dec_b     = (const float*)d_in[8];
    const float* w0        = (const float*)d_in[9];
    const float* w1        = (const float*)d_in[10];
    const float* w2        = (const float*)d_in[11];
    float* out = (float*)d_out;

    float* feats; cudaGetSymbolAddress((void**)&feats, g_feats);
    float* hbuf;  cudaGetSymbolAddress((void**)&hbuf,  g_h);
    float* sraw;  cudaGetSymbolAddress((void**)&sraw,  g_sraw);

    k1a_scores<<<dim3(16, B_), 256>>>(bert, input_ids, senti_w, senti_b, out, feats, sraw);
    k1b_att   <<<dim3(3, B_), 256>>>(bert, length, sraw, feats);
    k2_dense  <<<dim3(B_ / BM, NDIM / BN), 256>>>(feats, dense_w, dense_b, hbuf);
    k3_decoder<<<B_, 672>>>(hbuf, dec_w, dec_b, w0, w1, w2, out);
}